// round 8
// baseline (speedup 1.0000x reference)
#include <cuda_runtime.h>
#include <cstdint>
#include <cstddef>

typedef unsigned long long ull;

// ---------------- constants ----------------
#define BB   256
#define SS   512
#define DD   200
#define HH   256
#define NJ   1024          // 4*H packed gate columns
#define NGRP 16            // batch groups (16 rows each)
#define NCOL 16            // column-group CTAs per batch group (16 hidden cols each)

// ---------------- device scratch ----------------
__device__ float    g_G[134217728];    // [B][S][1024] gate preactivations (x part + bias)
__device__ float    g_Wxp[DD * NJ];    // packed x-weights  [200][1024]
__device__ float    g_Whp[16 * 16384]; // packed h-weights  [g2][256 k][64 j]
__device__ float    g_biasp[NJ];
__device__ float    g_hbuf[2 * 65536]; // [parity][group][k 256][row 16]
__device__ unsigned g_bar[NGRP];       // per-group monotonic barrier counters

// ---------------- helpers ----------------
__device__ __forceinline__ ull pk2(float lo, float hi) {
    ull r; asm("mov.b64 %0,{%1,%2};" : "=l"(r) : "f"(lo), "f"(hi)); return r;
}
__device__ __forceinline__ void upk2(ull v, float& lo, float& hi) {
    asm("mov.b64 {%0,%1},%2;" : "=f"(lo), "=f"(hi) : "l"(v));
}
__device__ __forceinline__ ull ffma2(ull a, ull b, ull c) {
    ull d; asm("fma.rn.f32x2 %0,%1,%2,%3;" : "=l"(d) : "l"(a), "l"(b), "l"(c)); return d;
}
__device__ __forceinline__ float sigf(float x) {
    return __fdividef(1.0f, 1.0f + __expf(-x));
}
__device__ __forceinline__ float tanhfast(float x) {
    return __fdividef(2.0f, 1.0f + __expf(-2.0f * x)) - 1.0f;
}
__device__ __forceinline__ unsigned ldacq(const unsigned* p) {
    unsigned v;
    asm volatile("ld.global.acquire.gpu.u32 %0,[%1];" : "=r"(v) : "l"(p) : "memory");
    return v;
}
__device__ __forceinline__ void red_release(unsigned* p) {
    asm volatile("red.release.gpu.global.add.u32 [%0], %1;" :: "l"(p), "r"(1u) : "memory");
}

// ---------------- kernel 0: pack weights ----------------
// j = g2*64 + c*4 + gate  (g2: col-CTA 0..15, c: col-in-CTA 0..15, gate: i,f,o,z)
__global__ void k_pack(const float* __restrict__ Wi, const float* __restrict__ Wf,
                       const float* __restrict__ Wo, const float* __restrict__ Wz,
                       const float* __restrict__ bi, const float* __restrict__ bf,
                       const float* __restrict__ bo, const float* __restrict__ bz) {
    int idx = blockIdx.x * blockDim.x + threadIdx.x;
    if (idx < 456 * NJ) {
        int k = idx >> 10;
        int j = idx & (NJ - 1);
        int gate = j & 3;
        int c    = (j >> 2) & 15;
        int g2   = j >> 6;
        int col  = g2 * 16 + c;
        const float* W = (gate == 0) ? Wi : (gate == 1) ? Wf : (gate == 2) ? Wo : Wz;
        float v = W[k * HH + col];
        if (k < DD) g_Wxp[k * NJ + j] = v;
        else        g_Whp[g2 * 16384 + (k - DD) * 64 + (j & 63)] = v;
    }
    if (idx < NJ) {
        int gate = idx & 3;
        int c    = (idx >> 2) & 15;
        int g2   = idx >> 6;
        int col  = g2 * 16 + c;
        const float* bb = (gate == 0) ? bi : (gate == 1) ? bf : (gate == 2) ? bo : bz;
        g_biasp[idx] = bb[col];
    }
}

// ---------------- kernel 1: reset barrier counters ----------------
__global__ void k_reset() {
    int i = threadIdx.x;
    if (i < NGRP) g_bar[i] = 0u;
}

// ---------------- kernel 2: G = X @ Wxp + bias ----------------
// m = b*512 + s. Tile 128x64, K-chunk 8, double-buffered, B stored dup (b,b).
#define G1_BM 128
#define G1_BN 64
#define G1_BK 8
__global__ void __launch_bounds__(256) k_gemm1(const float* __restrict__ x) {
    __shared__ __align__(16) float As[2][G1_BK][G1_BM];       // [k][row]
    __shared__ __align__(16) float Bs[2][G1_BK][G1_BN * 2];   // [k][col dup pairs]

    int tid = threadIdx.x;
    int m0 = blockIdx.y * G1_BM;
    int n0 = blockIdx.x * G1_BN;

    int arow = tid >> 1;
    int akq  = (tid & 1) * 4;
    const float* aptr = x + (size_t)(m0 + arow) * DD + akq;

    int bkk = tid >> 5;
    int bc2 = (tid & 31);
    const float* bptr = g_Wxp + (size_t)bkk * NJ + n0 + bc2 * 2;

    int tx = tid & 15;   // 4 n-cols
    int ty = tid >> 4;   // 8 m-rows

    ull acc[4][4];
#pragma unroll
    for (int i = 0; i < 4; ++i)
#pragma unroll
        for (int j = 0; j < 4; ++j) acc[i][j] = 0ull;

    float4 av = *(const float4*)aptr;
    float2 bv = *(const float2*)bptr;
    As[0][akq + 0][arow] = av.x;
    As[0][akq + 1][arow] = av.y;
    As[0][akq + 2][arow] = av.z;
    As[0][akq + 3][arow] = av.w;
    *(float4*)&Bs[0][bkk][bc2 * 4] = make_float4(bv.x, bv.x, bv.y, bv.y);

    for (int kc = 0; kc < 25; ++kc) {
        __syncthreads();
        int cur = kc & 1;
        if (kc < 24) {
            av = *(const float4*)(aptr + (kc + 1) * G1_BK);
            bv = *(const float2*)(bptr + (size_t)(kc + 1) * G1_BK * NJ);
        }
#pragma unroll
        for (int kk = 0; kk < G1_BK; ++kk) {
            const ulonglong2* ap2 = (const ulonglong2*)&As[cur][kk][ty * 8];
            ulonglong2 aA = ap2[0], aB = ap2[1];
            const ulonglong2* bp2 = (const ulonglong2*)&Bs[cur][kk][tx * 8];
            ulonglong2 bA = bp2[0], bB = bp2[1];
            acc[0][0] = ffma2(aA.x, bA.x, acc[0][0]); acc[0][1] = ffma2(aA.x, bA.y, acc[0][1]);
            acc[0][2] = ffma2(aA.x, bB.x, acc[0][2]); acc[0][3] = ffma2(aA.x, bB.y, acc[0][3]);
            acc[1][0] = ffma2(aA.y, bA.x, acc[1][0]); acc[1][1] = ffma2(aA.y, bA.y, acc[1][1]);
            acc[1][2] = ffma2(aA.y, bB.x, acc[1][2]); acc[1][3] = ffma2(aA.y, bB.y, acc[1][3]);
            acc[2][0] = ffma2(aB.x, bA.x, acc[2][0]); acc[2][1] = ffma2(aB.x, bA.y, acc[2][1]);
            acc[2][2] = ffma2(aB.x, bB.x, acc[2][2]); acc[2][3] = ffma2(aB.x, bB.y, acc[2][3]);
            acc[3][0] = ffma2(aB.y, bA.x, acc[3][0]); acc[3][1] = ffma2(aB.y, bA.y, acc[3][1]);
            acc[3][2] = ffma2(aB.y, bB.x, acc[3][2]); acc[3][3] = ffma2(aB.y, bB.y, acc[3][3]);
        }
        if (kc < 24) {
            int nxt = cur ^ 1;
            As[nxt][akq + 0][arow] = av.x;
            As[nxt][akq + 1][arow] = av.y;
            As[nxt][akq + 2][arow] = av.z;
            As[nxt][akq + 3][arow] = av.w;
            *(float4*)&Bs[nxt][bkk][bc2 * 4] = make_float4(bv.x, bv.x, bv.y, bv.y);
        }
    }

    float4 bias4 = *(const float4*)(g_biasp + n0 + tx * 4);
#pragma unroll
    for (int rp = 0; rp < 4; ++rp) {
        float4 r0, r1;
        upk2(acc[rp][0], r0.x, r1.x);
        upk2(acc[rp][1], r0.y, r1.y);
        upk2(acc[rp][2], r0.z, r1.z);
        upk2(acc[rp][3], r0.w, r1.w);
        r0.x += bias4.x; r0.y += bias4.y; r0.z += bias4.z; r0.w += bias4.w;
        r1.x += bias4.x; r1.y += bias4.y; r1.z += bias4.z; r1.w += bias4.w;
        size_t mrow = (size_t)m0 + ty * 8 + rp * 2;
        __stcs((float4*)(g_G + mrow * NJ + n0 + tx * 4), r0);
        __stcs((float4*)(g_G + (mrow + 1) * NJ + n0 + tx * 4), r1);
    }
}

// ---------------- kernel 3: persistent recurrence, 2 CTAs/SM ----------------
// 256 CTAs = 16 groups x 16 col-CTAs. thread = 1 row x 4 gate cols (1 hidden col).
// smem: Ws 65536B + stage 2 x 20480B = 106496B -> occupancy 2 (latency hiding
// across independent groups). Sync: proven tid0 acquire-poll + red.release.
#define WS_F  16384                      // 256*64 floats
#define ST_F  5120                       // 256*20 floats per parity (pad 20)
#define REC_SMEM_BYTES ((WS_F + 2 * ST_F) * 4)
__global__ void __launch_bounds__(256, 2) k_rec(const float* __restrict__ mask,
                                                float* __restrict__ out) {
    extern __shared__ __align__(16) float sm[];
    float* Ws  = sm;                     // [256 k][64 j]
    float* st0 = sm + WS_F;              // [256 k][20] (16 rows + pad)
    float* st1 = st0 + ST_F;

    int tid = threadIdx.x;
    int grp = blockIdx.x >> 4;
    int g2  = blockIdx.x & 15;
    int row = tid & 15;
    int cq  = tid >> 4;                  // hidden col in slice 0..15

    // preload weight slice (once for all 512 steps)
    {
        const float4* wsrc = (const float4*)(g_Whp + (size_t)g2 * 16384);
        float4* wdst = (float4*)Ws;
        for (int i = tid; i < 4096; i += 256) wdst[i] = wsrc[i];
    }
    __syncthreads();

    int b = grp * 16 + row;
    float cst = 0.f, sum = 0.f, msum = 0.f;
    const float* gbase = g_G + (size_t)b * SS * NJ + g2 * 64 + cq * 4;
    const float* mbase = mask + (size_t)b * SS;
    unsigned* barp = &g_bar[grp];

    for (int s = 0; s < SS; ++s) {
        // prefetch this step's x-gate preactivations + mask (independent of h)
        float4 ga = __ldcs((const float4*)(gbase + (size_t)s * NJ));
        float mval = __ldcg(mbase + s);
        ull acc0 = pk2(ga.x, ga.y), acc1 = pk2(ga.z, ga.w);

        if (s) {
            // wait for all 16 CTAs of this group to have published h[s]
            if (tid == 0) {
                unsigned tgt = 16u * (unsigned)s;
                while (ldacq(barp) < tgt) {}
            }
            __syncthreads();

            // gather h[s]: thread owns k = tid; straight copy [k][row] -> stage
            float* stg = (s & 1) ? st1 : st0;
            {
                const float4* src =
                    (const float4*)(g_hbuf + ((size_t)(s & 1)) * 65536 +
                                    (size_t)grp * 4096 + (size_t)tid * 16);
                float4 v0 = __ldcg(src + 0);
                float4 v1 = __ldcg(src + 1);
                float4 v2 = __ldcg(src + 2);
                float4 v3 = __ldcg(src + 3);
                float4* dst = (float4*)(stg + tid * 20);
                dst[0] = v0; dst[1] = v1; dst[2] = v2; dst[3] = v3;
            }
            __syncthreads();

            // gates += h @ Wh : 1 row x 4 gate cols per thread
            const float* hb = stg + row;
            const float* wb = Ws + cq * 4;
#pragma unroll 8
            for (int k = 0; k < HH; ++k) {
                float hk = hb[k * 20];
                ull h2 = pk2(hk, hk);
                ulonglong2 w = *(const ulonglong2*)(wb + k * 64);
                acc0 = ffma2(h2, w.x, acc0);
                acc1 = ffma2(h2, w.y, acc1);
            }
        }

        // nonlinearity + state update (gate order i,f,o,z)
        float ai, af, ao, az;
        upk2(acc0, ai, af); upk2(acc1, ao, az);
        float i0 = sigf(ai), f0 = sigf(af), o0 = sigf(ao), z0 = tanhfast(az);
        cst = i0 * z0 + f0 * cst;
        float h0 = o0 * tanhfast(cst);
        sum += h0 * mval; msum += mval;

        // publish h[s+1] to mailbox [parity][grp][k][row], k = g2*16+cq
        if (s < SS - 1) {
            __stcg(g_hbuf + ((size_t)((s + 1) & 1)) * 65536 + (size_t)grp * 4096 +
                       (size_t)(g2 * 16 + cq) * 16 + row,
                   h0);
            __syncthreads();
            if (tid == 0) red_release(barp);
        }
    }

    out[(size_t)b * HH + g2 * 16 + cq] = sum * __fdividef(1.0f, msum);
}

// ---------------- launcher ----------------
extern "C" void kernel_launch(void* const* d_in, const int* in_sizes, int n_in,
                              void* d_out, int out_size) {
    const float* x    = (const float*)d_in[0];
    const float* mask = (const float*)d_in[1];
    const float* Wi   = (const float*)d_in[2];
    const float* bi   = (const float*)d_in[3];
    const float* Wf   = (const float*)d_in[4];
    const float* bf   = (const float*)d_in[5];
    const float* Wo   = (const float*)d_in[6];
    const float* bo   = (const float*)d_in[7];
    const float* Wz   = (const float*)d_in[8];
    const float* bz   = (const float*)d_in[9];
    float* out = (float*)d_out;

    cudaFuncSetAttribute(k_rec, cudaFuncAttributeMaxDynamicSharedMemorySize,
                         REC_SMEM_BYTES);

    k_pack<<<(456 * NJ + 255) / 256, 256>>>(Wi, Wf, Wo, Wz, bi, bf, bo, bz);
    k_reset<<<1, 32>>>();
    dim3 g1(NJ / G1_BN, (BB * SS) / G1_BM);
    k_gemm1<<<g1, 256>>>(x);
    k_rec<<<NGRP * NCOL, 256, REC_SMEM_BYTES>>>(mask, out);
}